// round 1
// baseline (speedup 1.0000x reference)
#include <cuda_runtime.h>
#include <math.h>

#define BETA  5.5f
#define NC    1000
#define NM    50
#define ND    1024
#define ND4   256

__device__ float g_qn[ND];
__device__ float g_logits[NC];

// ---------------------------------------------------------------------------
// Kernel 1: qn = l2norm(img_feat + mean(global_bias, axis=0)).  1 block x 1024.
// ---------------------------------------------------------------------------
__global__ void compute_qn_kernel(const float* __restrict__ img,
                                  const float* __restrict__ gb)
{
    const int d = threadIdx.x;            // 0..1023
    float s = 0.0f;
    #pragma unroll 4
    for (int c = 0; c < NC; ++c)
        s += gb[c * ND + d];              // coalesced column stream
    const float q = img[d] + s * (1.0f / (float)NC);

    // block reduce q*q over 1024 threads (32 warps)
    __shared__ float red[32];
    float v = q * q;
    #pragma unroll
    for (int o = 16; o; o >>= 1) v += __shfl_xor_sync(0xffffffffu, v, o);
    const int w = d >> 5, lane = d & 31;
    if (lane == 0) red[w] = v;
    __syncthreads();
    float tot = 0.0f;
    #pragma unroll
    for (int i = 0; i < 32; ++i) tot += red[i];

    g_qn[d] = q * rsqrtf(tot);
}

// ---------------------------------------------------------------------------
// Kernel 2: per-class attention + double-normalize + logit. grid=1000, blk=256.
// Each thread owns 4 consecutive floats (float4) of the D=1024 dimension.
// One pass over mem rows: joint reduction of {sum(mem), qn.K, |K|^2, |V|^2}.
// ---------------------------------------------------------------------------
__global__ __launch_bounds__(256)
void dualmem_main_kernel(const float* __restrict__ mem,
                         const float* __restrict__ van,
                         const float* __restrict__ gbk,
                         const float* __restrict__ gbv,
                         const float* __restrict__ ffn,
                         const float* __restrict__ img,
                         const float* __restrict__ scale)
{
    const int c    = blockIdx.x;
    const int t    = threadIdx.x;       // 0..255
    const int wid  = t >> 5;
    const int lane = t & 31;

    __shared__ float4 red[2][8];
    __shared__ float  red1[8];
    __shared__ float2 red2[8];

    const float4 qn = reinterpret_cast<const float4*>(g_qn)[t];
    const float4 bk = reinterpret_cast<const float4*>(gbk + (size_t)c * ND)[t];
    const float4 bv = reinterpret_cast<const float4*>(gbv + (size_t)c * ND)[t];

    const float4* mrow = reinterpret_cast<const float4*>(mem + (size_t)c * NM * ND);
    const float4* vrow = reinterpret_cast<const float4*>(van + (size_t)c * ND);

    float4 acc = make_float4(0.f, 0.f, 0.f, 0.f);

    for (int m = 0; m <= NM; ++m) {
        const float4* src = (m < NM) ? (mrow + (size_t)m * ND4) : vrow;
        const float4 x = src[t];

        const float4 K = make_float4(x.x + bk.x, x.y + bk.y, x.z + bk.z, x.w + bk.w);
        const float4 V = make_float4(x.x + bv.x, x.y + bv.y, x.z + bv.z, x.w + bv.w);

        float sm = x.x + x.y + x.z + x.w;
        float dq = qn.x * K.x + qn.y * K.y + qn.z * K.z + qn.w * K.w;
        float k2 = K.x * K.x + K.y * K.y + K.z * K.z + K.w * K.w;
        float v2 = V.x * V.x + V.y * V.y + V.z * V.z + V.w * V.w;

        #pragma unroll
        for (int o = 16; o; o >>= 1) {
            sm += __shfl_xor_sync(0xffffffffu, sm, o);
            dq += __shfl_xor_sync(0xffffffffu, dq, o);
            k2 += __shfl_xor_sync(0xffffffffu, k2, o);
            v2 += __shfl_xor_sync(0xffffffffu, v2, o);
        }
        const int b = m & 1;
        if (lane == 0) red[b][wid] = make_float4(sm, dq, k2, v2);
        __syncthreads();

        float4 tot = red[b][0];
        #pragma unroll
        for (int i = 1; i < 8; ++i) {
            const float4 r = red[b][i];
            tot.x += r.x; tot.y += r.y; tot.z += r.z; tot.w += r.w;
        }

        float wgt = 0.0f;
        if (tot.x != 0.0f) {                      // non-empty slot
            const float sim = __expf(-BETA * (1.0f - tot.y * rsqrtf(tot.z)));
            wgt = sim * rsqrtf(tot.w);
        }
        acc.x += wgt * V.x;
        acc.y += wgt * V.y;
        acc.z += wgt * V.z;
        acc.w += wgt * V.w;
    }

    // --- epilogue: adaptive = l2norm(acc); a = adaptive + ffn; l2norm; dot img
    // reduce |acc|^2
    float n1 = acc.x * acc.x + acc.y * acc.y + acc.z * acc.z + acc.w * acc.w;
    #pragma unroll
    for (int o = 16; o; o >>= 1) n1 += __shfl_xor_sync(0xffffffffu, n1, o);
    if (lane == 0) red1[wid] = n1;
    __syncthreads();
    float n1t = 0.0f;
    #pragma unroll
    for (int i = 0; i < 8; ++i) n1t += red1[i];
    const float rin1 = rsqrtf(n1t);

    const float4 f  = reinterpret_cast<const float4*>(ffn + (size_t)c * ND)[t];
    const float4 im = reinterpret_cast<const float4*>(img)[t];
    const float4 a  = make_float4(acc.x * rin1 + f.x, acc.y * rin1 + f.y,
                                  acc.z * rin1 + f.z, acc.w * rin1 + f.w);

    float n2 = a.x * a.x + a.y * a.y + a.z * a.z + a.w * a.w;
    float dp = a.x * im.x + a.y * im.y + a.z * im.z + a.w * im.w;
    #pragma unroll
    for (int o = 16; o; o >>= 1) {
        n2 += __shfl_xor_sync(0xffffffffu, n2, o);
        dp += __shfl_xor_sync(0xffffffffu, dp, o);
    }
    __syncthreads();                 // red1 done being read above
    if (lane == 0) red2[wid] = make_float2(n2, dp);
    __syncthreads();

    if (t == 0) {
        float n2t = 0.0f, dpt = 0.0f;
        #pragma unroll
        for (int i = 0; i < 8; ++i) { n2t += red2[i].x; dpt += red2[i].y; }
        g_logits[c] = expf(scale[0]) * dpt * rsqrtf(n2t);
    }
}

// ---------------------------------------------------------------------------
// Kernel 3: softmax over 1000 logits. 1 block x 1024.
// ---------------------------------------------------------------------------
__global__ void softmax_kernel(float* __restrict__ out)
{
    const int t = threadIdx.x;
    const float x = (t < NC) ? g_logits[t] : -INFINITY;

    __shared__ float redm[32];
    __shared__ float reds[32];
    const int w = t >> 5, lane = t & 31;

    float v = x;
    #pragma unroll
    for (int o = 16; o; o >>= 1) v = fmaxf(v, __shfl_xor_sync(0xffffffffu, v, o));
    if (lane == 0) redm[w] = v;
    __syncthreads();
    float mx = -INFINITY;
    #pragma unroll
    for (int i = 0; i < 32; ++i) mx = fmaxf(mx, redm[i]);

    const float e = (t < NC) ? expf(x - mx) : 0.0f;
    float s = e;
    #pragma unroll
    for (int o = 16; o; o >>= 1) s += __shfl_xor_sync(0xffffffffu, s, o);
    if (lane == 0) reds[w] = s;
    __syncthreads();
    float st = 0.0f;
    #pragma unroll
    for (int i = 0; i < 32; ++i) st += reds[i];

    if (t < NC) out[t] = e / st;
}

// ---------------------------------------------------------------------------
extern "C" void kernel_launch(void* const* d_in, const int* in_sizes, int n_in,
                              void* d_out, int out_size)
{
    const float* img   = (const float*)d_in[0];  // (1, 1024)
    const float* mem   = (const float*)d_in[1];  // (1000, 50, 1024)
    const float* van   = (const float*)d_in[2];  // (1000, 1, 1024)
    const float* gb    = (const float*)d_in[3];  // (1000, 1024)
    const float* gbk   = (const float*)d_in[4];  // (1000, 1024)
    const float* gbv   = (const float*)d_in[5];  // (1000, 1024)
    const float* ffn   = (const float*)d_in[6];  // (1000, 1024)
    const float* scale = (const float*)d_in[7];  // scalar

    compute_qn_kernel<<<1, 1024>>>(img, gb);
    dualmem_main_kernel<<<NC, 256>>>(mem, van, gbk, gbv, ffn, img, scale);
    softmax_kernel<<<1, 1024>>>((float*)d_out);
}

// round 2
// speedup vs baseline: 2.5906x; 2.5906x over previous
#include <cuda_runtime.h>
#include <math.h>

#define BETA  5.5f
#define NC    1000
#define NM    50
#define ND    1024
#define ND4   256
#define QB    125          // partial-sum blocks for qn (1000/8)
#define QROWS 8

__device__ float g_qn[ND];
__device__ float g_logits[NC];
__device__ float g_qpart[QB * ND];

// ---------------------------------------------------------------------------
// Kernel 1a: partial column sums of global_bias. grid=125, block=1024.
// block b sums rows [b*8, b*8+8) into g_qpart[b].
// ---------------------------------------------------------------------------
__global__ void qn_partial_kernel(const float* __restrict__ gb)
{
    const int d = threadIdx.x;
    const int b = blockIdx.x;
    const float* base = gb + (size_t)b * QROWS * ND + d;
    float s = 0.0f;
    #pragma unroll
    for (int r = 0; r < QROWS; ++r)
        s += base[r * ND];
    g_qpart[b * ND + d] = s;
}

// ---------------------------------------------------------------------------
// Kernel 1b: finish qn = l2norm(img + mean). 1 block x 1024.
// ---------------------------------------------------------------------------
__global__ void qn_finish_kernel(const float* __restrict__ img)
{
    const int d = threadIdx.x;
    float s = 0.0f;
    #pragma unroll 5
    for (int b = 0; b < QB; ++b)
        s += g_qpart[b * ND + d];
    const float q = img[d] + s * (1.0f / (float)NC);

    __shared__ float red[32];
    float v = q * q;
    #pragma unroll
    for (int o = 16; o; o >>= 1) v += __shfl_xor_sync(0xffffffffu, v, o);
    const int w = d >> 5, lane = d & 31;
    if (lane == 0) red[w] = v;
    __syncthreads();
    float tot = 0.0f;
    #pragma unroll
    for (int i = 0; i < 32; ++i) tot += red[i];

    g_qn[d] = q * rsqrtf(tot);
}

// ---------------------------------------------------------------------------
// Kernel 2: per-class attention. grid=1000, block=256 (1 float4/thread).
// 2-row unroll with register prefetch; 1 barrier per 2 rows.
// ---------------------------------------------------------------------------
__global__ __launch_bounds__(256)
void dualmem_main_kernel(const float* __restrict__ mem,
                         const float* __restrict__ van,
                         const float* __restrict__ gbk,
                         const float* __restrict__ gbv,
                         const float* __restrict__ ffn,
                         const float* __restrict__ img,
                         const float* __restrict__ scale)
{
    const int c    = blockIdx.x;
    const int t    = threadIdx.x;
    const int wid  = t >> 5;
    const int lane = t & 31;

    __shared__ float4 red[2][2][8];     // [phase][row-in-pair][warp]
    __shared__ float  red1[8];
    __shared__ float2 red2[8];

    const float4 qn = reinterpret_cast<const float4*>(g_qn)[t];
    const float4 bk = reinterpret_cast<const float4*>(gbk + (size_t)c * ND)[t];
    const float4 bv = reinterpret_cast<const float4*>(gbv + (size_t)c * ND)[t];

    const float4* mrow = reinterpret_cast<const float4*>(mem + (size_t)c * NM * ND);
    const float4* vrow = reinterpret_cast<const float4*>(van + (size_t)c * ND);

    float4 acc = make_float4(0.f, 0.f, 0.f, 0.f);

    float4 x0 = mrow[0 * ND4 + t];
    float4 x1 = mrow[1 * ND4 + t];

    int p = 0;
    for (int m = 0; m < NM; m += 2, p ^= 1) {
        // prefetch next pair (or the vanilla row) before any dependent work
        float4 n0, n1;
        if (m + 3 < NM) {
            n0 = mrow[(size_t)(m + 2) * ND4 + t];
            n1 = mrow[(size_t)(m + 3) * ND4 + t];
        } else {
            n0 = vrow[t];           // m+2 == NM: vanilla row
            n1 = make_float4(0.f, 0.f, 0.f, 0.f);
        }

        const float4 K0 = make_float4(x0.x + bk.x, x0.y + bk.y, x0.z + bk.z, x0.w + bk.w);
        const float4 V0 = make_float4(x0.x + bv.x, x0.y + bv.y, x0.z + bv.z, x0.w + bv.w);
        const float4 K1 = make_float4(x1.x + bk.x, x1.y + bk.y, x1.z + bk.z, x1.w + bk.w);
        const float4 V1 = make_float4(x1.x + bv.x, x1.y + bv.y, x1.z + bv.z, x1.w + bv.w);

        float sm0 = x0.x + x0.y + x0.z + x0.w;
        float dq0 = qn.x * K0.x + qn.y * K0.y + qn.z * K0.z + qn.w * K0.w;
        float k20 = K0.x * K0.x + K0.y * K0.y + K0.z * K0.z + K0.w * K0.w;
        float v20 = V0.x * V0.x + V0.y * V0.y + V0.z * V0.z + V0.w * V0.w;
        float sm1 = x1.x + x1.y + x1.z + x1.w;
        float dq1 = qn.x * K1.x + qn.y * K1.y + qn.z * K1.z + qn.w * K1.w;
        float k21 = K1.x * K1.x + K1.y * K1.y + K1.z * K1.z + K1.w * K1.w;
        float v21 = V1.x * V1.x + V1.y * V1.y + V1.z * V1.z + V1.w * V1.w;

        #pragma unroll
        for (int o = 16; o; o >>= 1) {
            sm0 += __shfl_xor_sync(0xffffffffu, sm0, o);
            dq0 += __shfl_xor_sync(0xffffffffu, dq0, o);
            k20 += __shfl_xor_sync(0xffffffffu, k20, o);
            v20 += __shfl_xor_sync(0xffffffffu, v20, o);
            sm1 += __shfl_xor_sync(0xffffffffu, sm1, o);
            dq1 += __shfl_xor_sync(0xffffffffu, dq1, o);
            k21 += __shfl_xor_sync(0xffffffffu, k21, o);
            v21 += __shfl_xor_sync(0xffffffffu, v21, o);
        }
        if (lane == 0) {
            red[p][0][wid] = make_float4(sm0, dq0, k20, v20);
            red[p][1][wid] = make_float4(sm1, dq1, k21, v21);
        }
        __syncthreads();

        float4 t0 = red[p][0][0], t1 = red[p][1][0];
        #pragma unroll
        for (int i = 1; i < 8; ++i) {
            const float4 a = red[p][0][i], b = red[p][1][i];
            t0.x += a.x; t0.y += a.y; t0.z += a.z; t0.w += a.w;
            t1.x += b.x; t1.y += b.y; t1.z += b.z; t1.w += b.w;
        }

        float w0 = 0.0f, w1 = 0.0f;
        if (t0.x != 0.0f)
            w0 = __expf(-BETA * (1.0f - t0.y * rsqrtf(t0.z))) * rsqrtf(t0.w);
        if (t1.x != 0.0f)
            w1 = __expf(-BETA * (1.0f - t1.y * rsqrtf(t1.z))) * rsqrtf(t1.w);

        acc.x += w0 * V0.x + w1 * V1.x;
        acc.y += w0 * V0.y + w1 * V1.y;
        acc.z += w0 * V0.z + w1 * V1.z;
        acc.w += w0 * V0.w + w1 * V1.w;

        x0 = n0; x1 = n1;
    }

    // --- vanilla row (in x0) ---
    {
        __syncthreads();   // guard red buffer reuse
        const float4 K = make_float4(x0.x + bk.x, x0.y + bk.y, x0.z + bk.z, x0.w + bk.w);
        const float4 V = make_float4(x0.x + bv.x, x0.y + bv.y, x0.z + bv.z, x0.w + bv.w);
        float sm = x0.x + x0.y + x0.z + x0.w;
        float dq = qn.x * K.x + qn.y * K.y + qn.z * K.z + qn.w * K.w;
        float k2 = K.x * K.x + K.y * K.y + K.z * K.z + K.w * K.w;
        float v2 = V.x * V.x + V.y * V.y + V.z * V.z + V.w * V.w;
        #pragma unroll
        for (int o = 16; o; o >>= 1) {
            sm += __shfl_xor_sync(0xffffffffu, sm, o);
            dq += __shfl_xor_sync(0xffffffffu, dq, o);
            k2 += __shfl_xor_sync(0xffffffffu, k2, o);
            v2 += __shfl_xor_sync(0xffffffffu, v2, o);
        }
        if (lane == 0) red[0][0][wid] = make_float4(sm, dq, k2, v2);
        __syncthreads();
        float4 tt = red[0][0][0];
        #pragma unroll
        for (int i = 1; i < 8; ++i) {
            const float4 r = red[0][0][i];
            tt.x += r.x; tt.y += r.y; tt.z += r.z; tt.w += r.w;
        }
        float w = 0.0f;
        if (tt.x != 0.0f)
            w = __expf(-BETA * (1.0f - tt.y * rsqrtf(tt.z))) * rsqrtf(tt.w);
        acc.x += w * V.x; acc.y += w * V.y; acc.z += w * V.z; acc.w += w * V.w;
    }

    // --- epilogue ---
    float n1 = acc.x * acc.x + acc.y * acc.y + acc.z * acc.z + acc.w * acc.w;
    #pragma unroll
    for (int o = 16; o; o >>= 1) n1 += __shfl_xor_sync(0xffffffffu, n1, o);
    if (lane == 0) red1[wid] = n1;
    __syncthreads();
    float n1t = 0.0f;
    #pragma unroll
    for (int i = 0; i < 8; ++i) n1t += red1[i];
    const float rin1 = rsqrtf(n1t);

    const float4 f  = reinterpret_cast<const float4*>(ffn + (size_t)c * ND)[t];
    const float4 im = reinterpret_cast<const float4*>(img)[t];
    const float4 a  = make_float4(acc.x * rin1 + f.x, acc.y * rin1 + f.y,
                                  acc.z * rin1 + f.z, acc.w * rin1 + f.w);

    float n2 = a.x * a.x + a.y * a.y + a.z * a.z + a.w * a.w;
    float dp = a.x * im.x + a.y * im.y + a.z * im.z + a.w * im.w;
    #pragma unroll
    for (int o = 16; o; o >>= 1) {
        n2 += __shfl_xor_sync(0xffffffffu, n2, o);
        dp += __shfl_xor_sync(0xffffffffu, dp, o);
    }
    __syncthreads();
    if (lane == 0) red2[wid] = make_float2(n2, dp);
    __syncthreads();

    if (t == 0) {
        float n2t = 0.0f, dpt = 0.0f;
        #pragma unroll
        for (int i = 0; i < 8; ++i) { n2t += red2[i].x; dpt += red2[i].y; }
        g_logits[c] = expf(scale[0]) * dpt * rsqrtf(n2t);
    }
}

// ---------------------------------------------------------------------------
// Kernel 3: softmax over 1000 logits. 1 block x 1024.
// ---------------------------------------------------------------------------
__global__ void softmax_kernel(float* __restrict__ out)
{
    const int t = threadIdx.x;
    const float x = (t < NC) ? g_logits[t] : -INFINITY;

    __shared__ float redm[32];
    __shared__ float reds[32];
    const int w = t >> 5, lane = t & 31;

    float v = x;
    #pragma unroll
    for (int o = 16; o; o >>= 1) v = fmaxf(v, __shfl_xor_sync(0xffffffffu, v, o));
    if (lane == 0) redm[w] = v;
    __syncthreads();
    float mx = -INFINITY;
    #pragma unroll
    for (int i = 0; i < 32; ++i) mx = fmaxf(mx, redm[i]);

    const float e = (t < NC) ? expf(x - mx) : 0.0f;
    float s = e;
    #pragma unroll
    for (int o = 16; o; o >>= 1) s += __shfl_xor_sync(0xffffffffu, s, o);
    if (lane == 0) reds[w] = s;
    __syncthreads();
    float st = 0.0f;
    #pragma unroll
    for (int i = 0; i < 32; ++i) st += reds[i];

    if (t < NC) out[t] = e / st;
}

// ---------------------------------------------------------------------------
extern "C" void kernel_launch(void* const* d_in, const int* in_sizes, int n_in,
                              void* d_out, int out_size)
{
    const float* img   = (const float*)d_in[0];  // (1, 1024)
    const float* mem   = (const float*)d_in[1];  // (1000, 50, 1024)
    const float* van   = (const float*)d_in[2];  // (1000, 1, 1024)
    const float* gb    = (const float*)d_in[3];  // (1000, 1024)
    const float* gbk   = (const float*)d_in[4];  // (1000, 1024)
    const float* gbv   = (const float*)d_in[5];  // (1000, 1024)
    const float* ffn   = (const float*)d_in[6];  // (1000, 1024)
    const float* scale = (const float*)d_in[7];  // scalar

    qn_partial_kernel<<<QB, 1024>>>(gb);
    qn_finish_kernel<<<1, 1024>>>(img);
    dualmem_main_kernel<<<NC, 256>>>(mem, van, gbk, gbv, ffn, img, scale);
    softmax_kernel<<<1, 1024>>>((float*)d_out);
}

// round 3
// speedup vs baseline: 3.6831x; 1.4217x over previous
#include <cuda_runtime.h>
#include <math.h>

#define BETA  5.5f
#define NC    1000
#define NM    50
#define ND    1024
#define ND4   256
#define QB    125
#define QROWS 8

__device__ __align__(16) float g_qn[ND];
__device__ float g_logits[NC];
__device__ float g_qpart[QB * ND];
__device__ unsigned int g_ctr_q = 0;
__device__ unsigned int g_ctr_m = 0;

// ---------------------------------------------------------------------------
// Kernel 1: qn = l2norm(img + mean(global_bias,0)). grid=125 x 1024.
// Partial column sums; the last block to finish reduces + normalizes.
// ---------------------------------------------------------------------------
__global__ void qn_kernel(const float* __restrict__ gb,
                          const float* __restrict__ img)
{
    const int d = threadIdx.x;
    const int b = blockIdx.x;
    const float* base = gb + (size_t)b * QROWS * ND + d;
    float s = 0.0f;
    #pragma unroll
    for (int r = 0; r < QROWS; ++r) s += base[r * ND];
    g_qpart[b * ND + d] = s;

    __shared__ unsigned int ticket;
    __threadfence();
    __syncthreads();
    if (d == 0) ticket = atomicAdd(&g_ctr_q, 1u);
    __syncthreads();
    if (ticket != QB - 1) return;

    // last block: finish
    float tsum = 0.0f;
    #pragma unroll 5
    for (int bb = 0; bb < QB; ++bb) tsum += g_qpart[bb * ND + d];
    const float q = img[d] + tsum * (1.0f / (float)NC);

    __shared__ float red[32];
    float v = q * q;
    #pragma unroll
    for (int o = 16; o; o >>= 1) v += __shfl_xor_sync(0xffffffffu, v, o);
    const int w = d >> 5, lane = d & 31;
    if (lane == 0) red[w] = v;
    __syncthreads();
    float tot = 0.0f;
    #pragma unroll
    for (int i = 0; i < 32; ++i) tot += red[i];

    g_qn[d] = q * rsqrtf(tot);
    if (d == 0) g_ctr_q = 0;     // reset for graph replay
}

// ---------------------------------------------------------------------------
// Kernel 2: per-class attention, warp-per-row, barrier-free mainloop.
// grid=1000, block=128 (4 warps). Lane l owns float4 dims {j*32+l : j=0..7}.
// Last block runs the softmax over g_logits.
// ---------------------------------------------------------------------------
__global__ void __launch_bounds__(128)
dualmem_main_kernel(const float* __restrict__ mem,
                    const float* __restrict__ van,
                    const float* __restrict__ gbk,
                    const float* __restrict__ gbv,
                    const float* __restrict__ ffn,
                    const float* __restrict__ img,
                    const float* __restrict__ scale,
                    float* __restrict__ out)
{
    const int c    = blockIdx.x;
    const int t    = threadIdx.x;       // 0..127
    const int wi   = t >> 5;
    const int lane = t & 31;

    __shared__ float4 qn_s[ND4];
    __shared__ float4 bk_s[ND4];
    __shared__ float4 bv_s[ND4];
    __shared__ float4 accs[4][ND4];
    __shared__ float  sw_s[4];
    __shared__ float4 redc[4];
    __shared__ float  red1[4];
    __shared__ float2 red2[4];
    __shared__ float  redm[4], reds[4];
    __shared__ unsigned int ticket;

    const float4* qn4  = (const float4*)g_qn;
    const float4* gbk4 = (const float4*)(gbk + (size_t)c * ND);
    const float4* gbv4 = (const float4*)(gbv + (size_t)c * ND);
    const float4* mem4 = (const float4*)(mem + (size_t)c * NM * ND);
    const float4* van4 = (const float4*)(van + (size_t)c * ND);

    // --- prologue: stage qn/bk/bv to smem, per-class constants ---
    float pqk = 0.0f, pkk = 0.0f, pvv = 0.0f;
    #pragma unroll
    for (int r = 0; r < 2; ++r) {
        const int idx = t + r * 128;
        const float4 q = qn4[idx];
        const float4 k = gbk4[idx];
        const float4 v = gbv4[idx];
        qn_s[idx] = q; bk_s[idx] = k; bv_s[idx] = v;
        pqk += q.x*k.x + q.y*k.y + q.z*k.z + q.w*k.w;
        pkk += k.x*k.x + k.y*k.y + k.z*k.z + k.w*k.w;
        pvv += v.x*v.x + v.y*v.y + v.z*v.z + v.w*v.w;
    }
    #pragma unroll
    for (int o = 16; o; o >>= 1) {
        pqk += __shfl_xor_sync(0xffffffffu, pqk, o);
        pkk += __shfl_xor_sync(0xffffffffu, pkk, o);
        pvv += __shfl_xor_sync(0xffffffffu, pvv, o);
    }
    if (lane == 0) redc[wi] = make_float4(pqk, pkk, pvv, 0.0f);
    __syncthreads();
    float qk_c = 0.0f, kk_c = 0.0f, vv_c = 0.0f;
    #pragma unroll
    for (int i = 0; i < 4; ++i) {
        qk_c += redc[i].x; kk_c += redc[i].y; vv_c += redc[i].z;
    }

    // --- mainloop: warp wi handles rows m = wi, wi+4, ..., row NM = vanilla ---
    float4 acc[8];
    #pragma unroll
    for (int j = 0; j < 8; ++j) acc[j] = make_float4(0.f, 0.f, 0.f, 0.f);
    float sw = 0.0f;

    float4 xr[8], xn[8];
    {
        const float4* rp = (wi < NM) ? (mem4 + (size_t)wi * ND4) : van4;
        #pragma unroll
        for (int j = 0; j < 8; ++j) xr[j] = rp[j * 32 + lane];
    }

    int m = wi;
    while (true) {
        const int  mn = m + 4;
        const bool hn = (mn <= NM);
        if (hn) {
            const float4* rq = (mn < NM) ? (mem4 + (size_t)mn * ND4) : van4;
            #pragma unroll
            for (int j = 0; j < 8; ++j) xn[j] = rq[j * 32 + lane];
        }

        float xx = 0.0f, qx = 0.0f, xk = 0.0f, xv = 0.0f;
        #pragma unroll
        for (int j = 0; j < 8; ++j) {
            const float4 x = xr[j];
            const float4 q = qn_s[j * 32 + lane];
            const float4 k = bk_s[j * 32 + lane];
            const float4 v = bv_s[j * 32 + lane];
            xx += x.x*x.x + x.y*x.y + x.z*x.z + x.w*x.w;
            qx += q.x*x.x + q.y*x.y + q.z*x.z + q.w*x.w;
            xk += k.x*x.x + k.y*x.y + k.z*x.z + k.w*x.w;
            xv += v.x*x.x + v.y*x.y + v.z*x.z + v.w*x.w;
        }
        #pragma unroll
        for (int o = 16; o; o >>= 1) {
            xx += __shfl_xor_sync(0xffffffffu, xx, o);
            qx += __shfl_xor_sync(0xffffffffu, qx, o);
            xk += __shfl_xor_sync(0xffffffffu, xk, o);
            xv += __shfl_xor_sync(0xffffffffu, xv, o);
        }

        float w = 0.0f;
        if (xx != 0.0f) {              // all-zero row <=> |x|^2 == 0
            const float dq = qx + qk_c;
            const float k2 = xx + 2.0f * xk + kk_c;
            const float v2 = xx + 2.0f * xv + vv_c;
            w = __expf(-BETA * (1.0f - dq * rsqrtf(k2))) * rsqrtf(v2);
        }
        sw += w;
        #pragma unroll
        for (int j = 0; j < 8; ++j) {
            acc[j].x += w * xr[j].x;
            acc[j].y += w * xr[j].y;
            acc[j].z += w * xr[j].z;
            acc[j].w += w * xr[j].w;
        }

        if (!hn) break;
        #pragma unroll
        for (int j = 0; j < 8; ++j) xr[j] = xn[j];
        m = mn;
    }

    // --- combine warps: acc_total = sum_w acc + sw_total * bv ---
    #pragma unroll
    for (int j = 0; j < 8; ++j) accs[wi][j * 32 + lane] = acc[j];
    if (lane == 0) sw_s[wi] = sw;
    __syncthreads();

    const float swt = sw_s[0] + sw_s[1] + sw_s[2] + sw_s[3];
    float4 a0, a1;
    {
        const int i0 = t, i1 = t + 128;
        float4 s0 = accs[0][i0], s1 = accs[0][i1];
        #pragma unroll
        for (int w = 1; w < 4; ++w) {
            const float4 p = accs[w][i0], q = accs[w][i1];
            s0.x += p.x; s0.y += p.y; s0.z += p.z; s0.w += p.w;
            s1.x += q.x; s1.y += q.y; s1.z += q.z; s1.w += q.w;
        }
        const float4 b0 = bv_s[i0], b1 = bv_s[i1];
        a0 = make_float4(s0.x + swt*b0.x, s0.y + swt*b0.y, s0.z + swt*b0.z, s0.w + swt*b0.w);
        a1 = make_float4(s1.x + swt*b1.x, s1.y + swt*b1.y, s1.z + swt*b1.z, s1.w + swt*b1.w);
    }

    // l2norm(acc)
    float n1 = a0.x*a0.x + a0.y*a0.y + a0.z*a0.z + a0.w*a0.w
             + a1.x*a1.x + a1.y*a1.y + a1.z*a1.z + a1.w*a1.w;
    #pragma unroll
    for (int o = 16; o; o >>= 1) n1 += __shfl_xor_sync(0xffffffffu, n1, o);
    if (lane == 0) red1[wi] = n1;
    __syncthreads();
    const float rin1 = rsqrtf(red1[0] + red1[1] + red1[2] + red1[3]);

    // + ffn, l2norm, dot img
    const float4* ffn4 = (const float4*)(ffn + (size_t)c * ND);
    const float4* img4 = (const float4*)img;
    const float4 f0 = ffn4[t], f1 = ffn4[t + 128];
    const float4 i0 = img4[t], i1 = img4[t + 128];
    const float4 af0 = make_float4(a0.x*rin1 + f0.x, a0.y*rin1 + f0.y,
                                   a0.z*rin1 + f0.z, a0.w*rin1 + f0.w);
    const float4 af1 = make_float4(a1.x*rin1 + f1.x, a1.y*rin1 + f1.y,
                                   a1.z*rin1 + f1.z, a1.w*rin1 + f1.w);

    float n2 = af0.x*af0.x + af0.y*af0.y + af0.z*af0.z + af0.w*af0.w
             + af1.x*af1.x + af1.y*af1.y + af1.z*af1.z + af1.w*af1.w;
    float dp = af0.x*i0.x + af0.y*i0.y + af0.z*i0.z + af0.w*i0.w
             + af1.x*i1.x + af1.y*i1.y + af1.z*i1.z + af1.w*i1.w;
    #pragma unroll
    for (int o = 16; o; o >>= 1) {
        n2 += __shfl_xor_sync(0xffffffffu, n2, o);
        dp += __shfl_xor_sync(0xffffffffu, dp, o);
    }
    if (lane == 0) red2[wi] = make_float2(n2, dp);
    __syncthreads();

    if (t == 0) {
        float n2t = 0.0f, dpt = 0.0f;
        #pragma unroll
        for (int i = 0; i < 4; ++i) { n2t += red2[i].x; dpt += red2[i].y; }
        g_logits[c] = expf(scale[0]) * dpt * rsqrtf(n2t);
    }

    // --- last block: softmax over g_logits into d_out ---
    __threadfence();
    __syncthreads();
    if (t == 0) ticket = atomicAdd(&g_ctr_m, 1u);
    __syncthreads();
    if (ticket != NC - 1) return;

    float x[8];
    #pragma unroll
    for (int k = 0; k < 8; ++k) {
        const int i = t + k * 128;
        x[k] = (i < NC) ? g_logits[i] : -INFINITY;
    }
    float mx = x[0];
    #pragma unroll
    for (int k = 1; k < 8; ++k) mx = fmaxf(mx, x[k]);
    #pragma unroll
    for (int o = 16; o; o >>= 1) mx = fmaxf(mx, __shfl_xor_sync(0xffffffffu, mx, o));
    if (lane == 0) redm[wi] = mx;
    __syncthreads();
    mx = fmaxf(fmaxf(redm[0], redm[1]), fmaxf(redm[2], redm[3]));

    float e[8];
    float es = 0.0f;
    #pragma unroll
    for (int k = 0; k < 8; ++k) {
        const int i = t + k * 128;
        e[k] = (i < NC) ? expf(x[k] - mx) : 0.0f;
        es += e[k];
    }
    #pragma unroll
    for (int o = 16; o; o >>= 1) es += __shfl_xor_sync(0xffffffffu, es, o);
    if (lane == 0) reds[wi] = es;
    __syncthreads();
    const float stot = reds[0] + reds[1] + reds[2] + reds[3];
    const float rst = 1.0f / stot;

    #pragma unroll
    for (int k = 0; k < 8; ++k) {
        const int i = t + k * 128;
        if (i < NC) out[i] = e[k] * rst;
    }
    if (t == 0) g_ctr_m = 0;     // reset for graph replay
}

// ---------------------------------------------------------------------------
extern "C" void kernel_launch(void* const* d_in, const int* in_sizes, int n_in,
                              void* d_out, int out_size)
{
    const float* img   = (const float*)d_in[0];  // (1, 1024)
    const float* mem   = (const float*)d_in[1];  // (1000, 50, 1024)
    const float* van   = (const float*)d_in[2];  // (1000, 1, 1024)
    const float* gb    = (const float*)d_in[3];  // (1000, 1024)
    const float* gbk   = (const float*)d_in[4];  // (1000, 1024)
    const float* gbv   = (const float*)d_in[5];  // (1000, 1024)
    const float* ffn   = (const float*)d_in[6];  // (1000, 1024)
    const float* scale = (const float*)d_in[7];  // scalar

    qn_kernel<<<QB, 1024>>>(gb, img);
    dualmem_main_kernel<<<NC, 128>>>(mem, van, gbk, gbv, ffn, img, scale,
                                     (float*)d_out);
}